// round 3
// baseline (speedup 1.0000x reference)
#include <cuda_runtime.h>
#include <cuda_fp16.h>
#include <cstdint>
#include <float.h>

#define NTOK 32768
#define DIMD 256
#define KVOC 8192
#define MTILES 256          // m-tiles of 128 tokens
#define NTIL   64           // n-tiles of 128 codewords
#define TAU  0.08f

// ---- device scratch ----
__device__ __half g_Ah[(size_t)NTOK * DIMD];   // 16 MB fp16 tokens
__device__ __half g_Bh[(size_t)KVOC * DIMD];   // 4 MB fp16 vocab
__device__ float  g_vnorm[KVOC];               // 0.5*||v||^2 fp32
__device__ float  g_s1[(size_t)NTIL * NTOK];
__device__ float  g_s2[(size_t)NTIL * NTOK];
__device__ int    g_i1[(size_t)NTIL * NTOK];
__device__ int    g_idx[NTOK];
__device__ int    g_wl[NTOK];
__device__ int    g_wlcount;

// ---- smem offsets for gemm kernel ----
#define SO_A   0
#define SO_B   65536
#define SO_VN  131072
#define SO_R1  131584
#define SO_R2  133632
#define SO_RI  135680
#define SM_TOTAL 137728

// ============================ asm helpers ============================
__device__ __forceinline__ uint32_t smem_u32(const void* p) {
    uint32_t a;
    asm("{ .reg .u64 t; cvta.to.shared.u64 t, %1; cvt.u32.u64 %0, t; }"
        : "=r"(a) : "l"(p));
    return a;
}
__device__ __forceinline__ void cpasync16(uint32_t s, const void* g) {
    asm volatile("cp.async.cg.shared.global [%0], [%1], 16;" :: "r"(s), "l"(g));
}
#define CP_COMMIT() asm volatile("cp.async.commit_group;" ::: "memory")
#define CP_WAIT(N)  asm volatile("cp.async.wait_group " #N ";" ::: "memory")

__device__ __forceinline__ void ldsm4(uint32_t& r0, uint32_t& r1, uint32_t& r2,
                                      uint32_t& r3, uint32_t addr) {
    asm volatile("ldmatrix.sync.aligned.m8n8.x4.shared.b16 {%0,%1,%2,%3}, [%4];"
                 : "=r"(r0), "=r"(r1), "=r"(r2), "=r"(r3) : "r"(addr));
}
__device__ __forceinline__ void mma16816(float* d, const uint32_t* a,
                                         uint32_t b0, uint32_t b1) {
    asm volatile(
        "mma.sync.aligned.m16n8k16.row.col.f32.f16.f16.f32 "
        "{%0,%1,%2,%3},{%4,%5,%6,%7},{%8,%9},{%0,%1,%2,%3};"
        : "+f"(d[0]), "+f"(d[1]), "+f"(d[2]), "+f"(d[3])
        : "r"(a[0]), "r"(a[1]), "r"(a[2]), "r"(a[3]), "r"(b0), "r"(b1));
}
__device__ __forceinline__ uint32_t swz(uint32_t off) {
    return off ^ ((off >> 3) & 0x70);
}

// ============================ convert kernels ============================
__global__ void split_seq_kernel(const float* __restrict__ seq) {
    if (blockIdx.x == 0 && threadIdx.x == 0) g_wlcount = 0;
    int idx = blockIdx.x * blockDim.x + threadIdx.x;   // one float4 each
    int row = idx >> 6;
    int c4  = idx & 63;
    float4 x = ((const float4*)seq)[idx];
    __half2 a = __floats2half2_rn(x.x, x.y);
    __half2 b = __floats2half2_rn(x.z, x.w);
    uint2 u;
    u.x = *(uint32_t*)&a; u.y = *(uint32_t*)&b;
    *(uint2*)(g_Ah + (size_t)row * DIMD + c4 * 4) = u;
}

__global__ void split_vocab_kernel(const float* __restrict__ vocab) {
    int row  = blockIdx.x * 8 + (threadIdx.x >> 5);
    int lane = threadIdx.x & 31;
    const float4* v = (const float4*)(vocab + (size_t)row * DIMD);
    float s = 0.f;
    #pragma unroll
    for (int c4 = lane; c4 < 64; c4 += 32) {
        float4 x = v[c4];
        s += x.x*x.x + x.y*x.y + x.z*x.z + x.w*x.w;
        __half2 a = __floats2half2_rn(x.x, x.y);
        __half2 b = __floats2half2_rn(x.z, x.w);
        uint2 u;
        u.x = *(uint32_t*)&a; u.y = *(uint32_t*)&b;
        *(uint2*)(g_Bh + (size_t)row * DIMD + c4 * 4) = u;
    }
    #pragma unroll
    for (int o = 16; o; o >>= 1) s += __shfl_xor_sync(0xffffffffu, s, o);
    if (lane == 0) g_vnorm[row] = 0.5f * s;
}

// ============================ fp16 GEMM + fused top-2 ============================
__global__ __launch_bounds__(256, 1)
void gemm_kernel() {
    extern __shared__ char smem[];
    uint32_t sAu = smem_u32(smem);
    uint32_t sBu = sAu + SO_B;
    float* s_vn = (float*)(smem + SO_VN);
    float* r1a  = (float*)(smem + SO_R1);
    float* r2a  = (float*)(smem + SO_R2);
    int*   ria  = (int*)  (smem + SO_RI);

    const int tid = threadIdx.x, lane = tid & 31, wid = tid >> 5;
    const int wm = wid & 1, wn = wid >> 1;          // 2 x 4 warp grid
    const int bm = blockIdx.x & (MTILES - 1);
    const int bn = blockIdx.x >> 8;
    const int m0 = bm * 128, n0 = bn * 128;

    const char* Ab = (const char*)g_Ah + (size_t)m0 * 512;
    const char* Bb = (const char*)g_Bh + (size_t)n0 * 512;

    // issue all 4 k-chunks (each = A 16KB + B 16KB), one commit group each
    #pragma unroll
    for (int kc = 0; kc < 4; kc++) {
        #pragma unroll
        for (int q = 0; q < 4; q++) {
            int p = tid + 256 * q; int r = p >> 3, j = p & 7;
            cpasync16(sAu + kc * 16384 + swz(r * 128 + j * 16),
                      Ab + (size_t)r * 512 + kc * 128 + j * 16);
        }
        #pragma unroll
        for (int q = 0; q < 4; q++) {
            int p = tid + 256 * q; int r = p >> 3, j = p & 7;
            cpasync16(sBu + kc * 16384 + swz(r * 128 + j * 16),
                      Bb + (size_t)r * 512 + kc * 128 + j * 16);
        }
        CP_COMMIT();
    }
    if (tid < 128) s_vn[tid] = g_vnorm[n0 + tid];

    float acc[4][4][4];
    #pragma unroll
    for (int i = 0; i < 4; i++)
        #pragma unroll
        for (int j = 0; j < 4; j++)
            #pragma unroll
            for (int c = 0; c < 4; c++) acc[i][j][c] = 0.f;

#define COMPUTE_CHUNK(KC)                                                      \
    {                                                                          \
        uint32_t Abase = sAu + (KC) * 16384;                                   \
        uint32_t Bbase = sBu + (KC) * 16384;                                   \
        _Pragma("unroll")                                                      \
        for (int ks = 0; ks < 4; ks++) {                                       \
            uint32_t af[4][4];                                                 \
            _Pragma("unroll")                                                  \
            for (int mt = 0; mt < 4; mt++) {                                   \
                int row = wm * 64 + mt * 16 + (lane & 15);                     \
                uint32_t ad = Abase + swz(row * 128 + ks * 32 + (lane >> 4) * 16); \
                ldsm4(af[mt][0], af[mt][1], af[mt][2], af[mt][3], ad);         \
            }                                                                  \
            uint32_t bf[2][4];                                                 \
            _Pragma("unroll")                                                  \
            for (int np = 0; np < 2; np++) {                                   \
                int row = wn * 32 + np * 16 + (lane & 15);                     \
                uint32_t bd = Bbase + swz(row * 128 + ks * 32 + (lane >> 4) * 16); \
                ldsm4(bf[np][0], bf[np][1], bf[np][2], bf[np][3], bd);         \
            }                                                                  \
            _Pragma("unroll")                                                  \
            for (int mt = 0; mt < 4; mt++) {                                   \
                _Pragma("unroll")                                              \
                for (int nt = 0; nt < 4; nt++) {                               \
                    int np = nt >> 1, sub = nt & 1;                            \
                    mma16816(acc[mt][nt], af[mt], bf[np][sub], bf[np][sub + 2]); \
                }                                                              \
            }                                                                  \
        }                                                                      \
    }

    CP_WAIT(3); __syncthreads(); COMPUTE_CHUNK(0);
    CP_WAIT(2); __syncthreads(); COMPUTE_CHUNK(1);
    CP_WAIT(1); __syncthreads(); COMPUTE_CHUNK(2);
    CP_WAIT(0); __syncthreads(); COMPUTE_CHUNK(3);
#undef COMPUTE_CHUNK

    // ---- fused top-2 epilogue ----
    float m1[8], m2[8]; int i1[8];                 // slot = mt*2 + rowgroup
    #pragma unroll
    for (int s = 0; s < 8; s++) { m1[s] = FLT_MAX; m2[s] = FLT_MAX; i1[s] = 0x7FFFFFFF; }

    #pragma unroll
    for (int nt = 0; nt < 4; nt++) {
        int nloc_base = wn * 32 + (nt >> 1) * 16 + (nt & 1) * 8 + (lane & 3) * 2;
        #pragma unroll
        for (int c = 0; c < 2; c++) {
            int nloc = nloc_base + c;
            float vn = s_vn[nloc];
            int n = n0 + nloc;
            #pragma unroll
            for (int mt = 0; mt < 4; mt++) {
                #pragma unroll
                for (int rg = 0; rg < 2; rg++) {
                    int s_ = mt * 2 + rg;
                    float sc = vn - acc[mt][nt][rg * 2 + c];
                    if (sc < m1[s_]) { m2[s_] = m1[s_]; m1[s_] = sc; i1[s_] = n; }
                    else if (sc < m2[s_]) m2[s_] = sc;
                }
            }
        }
    }

    // quad reduce (cols live in lanes with same lane>>2)
    #pragma unroll
    for (int s = 0; s < 8; s++) {
        #pragma unroll
        for (int off = 1; off <= 2; off <<= 1) {
            float om1 = __shfl_xor_sync(0xffffffffu, m1[s], off);
            float om2 = __shfl_xor_sync(0xffffffffu, m2[s], off);
            int   oi  = __shfl_xor_sync(0xffffffffu, i1[s], off);
            if (om1 < m1[s] || (om1 == m1[s] && oi < i1[s])) {
                m2[s] = fminf(m1[s], om2); m1[s] = om1; i1[s] = oi;
            } else {
                m2[s] = fminf(m2[s], om1);
            }
        }
    }
    if ((lane & 3) == 0) {
        #pragma unroll
        for (int mt = 0; mt < 4; mt++)
            #pragma unroll
            for (int rg = 0; rg < 2; rg++) {
                int s_ = mt * 2 + rg;
                int row = wm * 64 + mt * 16 + rg * 8 + (lane >> 2);
                r1a[row * 4 + wn] = m1[s_];
                r2a[row * 4 + wn] = m2[s_];
                ria[row * 4 + wn] = i1[s_];
            }
    }
    __syncthreads();

    if (tid < 128) {
        float M1 = FLT_MAX, M2 = FLT_MAX; int I1 = 0x7FFFFFFF;
        #pragma unroll
        for (int w = 0; w < 4; w++) {
            float a1 = r1a[tid * 4 + w], a2 = r2a[tid * 4 + w];
            int   ai = ria[tid * 4 + w];
            if (a1 < M1 || (a1 == M1 && ai < I1)) {
                M2 = fminf(M1, a2); M1 = a1; I1 = ai;
            } else {
                M2 = fminf(M2, a1);
            }
        }
        int token = m0 + tid;
        g_s1[(size_t)bn * NTOK + token] = M1;
        g_s2[(size_t)bn * NTOK + token] = M2;
        g_i1[(size_t)bn * NTOK + token] = I1;
    }
}

// ============================ reduce + flag ============================
__global__ void reduce_kernel() {
    int t = blockIdx.x * blockDim.x + threadIdx.x;
    float m1 = FLT_MAX, m2 = FLT_MAX; int i1 = 0x7FFFFFFF;
    for (int nt = 0; nt < NTIL; nt++) {
        float s1 = g_s1[(size_t)nt * NTOK + t];
        float s2 = g_s2[(size_t)nt * NTOK + t];
        int   ii = g_i1[(size_t)nt * NTOK + t];
        if (s1 < m1 || (s1 == m1 && ii < i1)) {
            m2 = fminf(m1, s2); m1 = s1; i1 = ii;
        } else {
            m2 = fminf(m2, s1);
        }
    }
    g_idx[t] = i1;
    if (m2 - m1 < TAU) {
        int slot = atomicAdd(&g_wlcount, 1);
        g_wl[slot] = t;
    }
}

// ============================ exact fp32 cleanup (R1-style, indirect M) ===
#define CMT 128
#define CKC 32
#define CPAD 132
__global__ __launch_bounds__(256, 2)
void cleanup_kernel(const float* __restrict__ seq, const float* __restrict__ vocab) {
    __shared__ float As[CKC][CPAD];
    __shared__ float Bs[CKC][CPAD];
    __shared__ int   tk[CMT];

    int nf = g_wlcount;
    int m0 = blockIdx.x * CMT;
    if (m0 >= nf) return;

    const int tid = threadIdx.x;
    const int tm  = tid >> 4, tn = tid & 15;
    const int lk  = tid & 31, lm = tid >> 5;

    if (tid < CMT) {
        int w = m0 + tid;
        tk[tid] = g_wl[w < nf ? w : (nf - 1)];
    }
    __syncthreads();

    float minv[8]; int mini[8];
    #pragma unroll
    for (int i = 0; i < 8; i++) { minv[i] = FLT_MAX; mini[i] = 0; }

    for (int n0 = 0; n0 < KVOC; n0 += 128) {
        float accm[8][8];
        #pragma unroll
        for (int i = 0; i < 8; i++)
            #pragma unroll
            for (int j = 0; j < 8; j++) accm[i][j] = 0.f;

        for (int kc = 0; kc < DIMD; kc += CKC) {
            __syncthreads();
            #pragma unroll
            for (int m = lm; m < CMT; m += 8)
                As[lk][m] = seq[(size_t)tk[m] * DIMD + kc + lk];
            #pragma unroll
            for (int n = lm; n < 128; n += 8)
                Bs[lk][n] = vocab[(size_t)(n0 + n) * DIMD + kc + lk];
            __syncthreads();

            #pragma unroll 8
            for (int k = 0; k < CKC; k++) {
                float4 a0 = *(const float4*)&As[k][tm * 8];
                float4 a1 = *(const float4*)&As[k][tm * 8 + 4];
                float4 b0 = *(const float4*)&Bs[k][tn * 8];
                float4 b1 = *(const float4*)&Bs[k][tn * 8 + 4];
                float a[8] = {a0.x, a0.y, a0.z, a0.w, a1.x, a1.y, a1.z, a1.w};
                float b[8] = {b0.x, b0.y, b0.z, b0.w, b1.x, b1.y, b1.z, b1.w};
                #pragma unroll
                for (int i = 0; i < 8; i++)
                    #pragma unroll
                    for (int j = 0; j < 8; j++)
                        accm[i][j] += a[i] * b[j];
            }
        }
        #pragma unroll
        for (int j = 0; j < 8; j++) {
            int n = n0 + tn * 8 + j;
            float vn = g_vnorm[n];
            #pragma unroll
            for (int i = 0; i < 8; i++) {
                float sc = vn - accm[i][j];
                if (sc < minv[i]) { minv[i] = sc; mini[i] = n; }
            }
        }
    }
    #pragma unroll
    for (int off = 8; off; off >>= 1) {
        #pragma unroll
        for (int i = 0; i < 8; i++) {
            float ov = __shfl_down_sync(0xffffffffu, minv[i], off, 16);
            int   oi = __shfl_down_sync(0xffffffffu, mini[i], off, 16);
            if (ov < minv[i] || (ov == minv[i] && oi < mini[i])) {
                minv[i] = ov; mini[i] = oi;
            }
        }
    }
    if (tn == 0) {
        #pragma unroll
        for (int i = 0; i < 8; i++) {
            int w = m0 + tm * 8 + i;
            if (w < nf) g_idx[g_wl[w]] = mini[i];
        }
    }
}

// ============================ gather ============================
__global__ void gather_kernel(const float* __restrict__ vocab,
                              float* __restrict__ out, int write_idx) {
    int token = blockIdx.x * 4 + (threadIdx.x >> 6);
    int l     = threadIdx.x & 63;
    int idx   = g_idx[token];
    const float4* src = (const float4*)(vocab + (size_t)idx * DIMD);
    float4*       dst = (float4*)(out + (size_t)token * DIMD);
    dst[l] = src[l];
    if (write_idx && l == 0)
        out[(size_t)NTOK * DIMD + token] = (float)idx;
}

// ============================ launch ============================
extern "C" void kernel_launch(void* const* d_in, const int* in_sizes, int n_in,
                              void* d_out, int out_size) {
    const float* seq   = (const float*)d_in[0];
    const float* vocab = (const float*)d_in[1];
    float* out = (float*)d_out;
    int write_idx = (out_size >= NTOK * DIMD + NTOK) ? 1 : 0;

    cudaFuncSetAttribute(gemm_kernel,
                         cudaFuncAttributeMaxDynamicSharedMemorySize, SM_TOTAL);

    split_seq_kernel<<<(NTOK * DIMD / 4) / 256, 256>>>(seq);
    split_vocab_kernel<<<KVOC / 8, 256>>>(vocab);
    gemm_kernel<<<MTILES * NTIL, 256, SM_TOTAL>>>();
    reduce_kernel<<<NTOK / 128, 128>>>();
    cleanup_kernel<<<NTOK / CMT, 256>>>(seq, vocab);
    gather_kernel<<<NTOK / 4, 256>>>(vocab, out, write_idx);
}

// round 4
// speedup vs baseline: 3.1631x; 3.1631x over previous
#include <cuda_runtime.h>
#include <cuda_fp16.h>
#include <cstdint>
#include <float.h>

#define NTOK 32768
#define DIMD 256
#define KVOC 8192
#define MTILES 256          // m-tiles of 128 tokens
#define NTIL   64           // n-tiles of 128 codewords
#define TAU  0.08f

// ---- device scratch ----
__device__ __half g_Ah[(size_t)NTOK * DIMD];   // 16 MB fp16 tokens
__device__ __half g_Bh[(size_t)KVOC * DIMD];   // 4 MB fp16 vocab
__device__ float  g_vnorm[KVOC];               // 0.5*||v||^2 fp32
__device__ float  g_s1[(size_t)NTIL * NTOK];
__device__ float  g_s2[(size_t)NTIL * NTOK];
__device__ int    g_i1[(size_t)NTIL * NTOK];
__device__ int    g_idx[NTOK];
__device__ unsigned long long g_key[NTOK];
__device__ int    g_wl[NTOK];
__device__ int    g_wlcount;

// ---- smem offsets for gemm kernel ----
#define SO_A   0
#define SO_B   65536
#define SO_VN  131072
#define SO_R1  131584
#define SO_R2  133632
#define SO_RI  135680
#define SM_TOTAL 137728

// ============================ asm helpers ============================
__device__ __forceinline__ uint32_t smem_u32(const void* p) {
    uint32_t a;
    asm("{ .reg .u64 t; cvta.to.shared.u64 t, %1; cvt.u32.u64 %0, t; }"
        : "=r"(a) : "l"(p));
    return a;
}
__device__ __forceinline__ void cpasync16(uint32_t s, const void* g) {
    asm volatile("cp.async.cg.shared.global [%0], [%1], 16;" :: "r"(s), "l"(g));
}
#define CP_COMMIT() asm volatile("cp.async.commit_group;" ::: "memory")
#define CP_WAIT(N)  asm volatile("cp.async.wait_group " #N ";" ::: "memory")

__device__ __forceinline__ void ldsm4(uint32_t& r0, uint32_t& r1, uint32_t& r2,
                                      uint32_t& r3, uint32_t addr) {
    asm volatile("ldmatrix.sync.aligned.m8n8.x4.shared.b16 {%0,%1,%2,%3}, [%4];"
                 : "=r"(r0), "=r"(r1), "=r"(r2), "=r"(r3) : "r"(addr));
}
__device__ __forceinline__ void mma16816(float* d, const uint32_t* a,
                                         uint32_t b0, uint32_t b1) {
    asm volatile(
        "mma.sync.aligned.m16n8k16.row.col.f32.f16.f16.f32 "
        "{%0,%1,%2,%3},{%4,%5,%6,%7},{%8,%9},{%0,%1,%2,%3};"
        : "+f"(d[0]), "+f"(d[1]), "+f"(d[2]), "+f"(d[3])
        : "r"(a[0]), "r"(a[1]), "r"(a[2]), "r"(a[3]), "r"(b0), "r"(b1));
}
__device__ __forceinline__ uint32_t swz(uint32_t off) {
    return off ^ ((off >> 3) & 0x70);
}
// monotone float -> uint mapping (order preserving incl. negatives)
__device__ __forceinline__ uint32_t f2ord(float s) {
    uint32_t fb = __float_as_uint(s);
    return (fb & 0x80000000u) ? ~fb : (fb | 0x80000000u);
}

// ============================ convert kernels ============================
__global__ void split_seq_kernel(const float* __restrict__ seq) {
    if (blockIdx.x == 0 && threadIdx.x == 0) g_wlcount = 0;
    int idx = blockIdx.x * blockDim.x + threadIdx.x;   // one float4 each
    int row = idx >> 6;
    int c4  = idx & 63;
    float4 x = ((const float4*)seq)[idx];
    __half2 a = __floats2half2_rn(x.x, x.y);
    __half2 b = __floats2half2_rn(x.z, x.w);
    uint2 u;
    u.x = *(uint32_t*)&a; u.y = *(uint32_t*)&b;
    *(uint2*)(g_Ah + (size_t)row * DIMD + c4 * 4) = u;
}

__global__ void split_vocab_kernel(const float* __restrict__ vocab) {
    int row  = blockIdx.x * 8 + (threadIdx.x >> 5);
    int lane = threadIdx.x & 31;
    const float4* v = (const float4*)(vocab + (size_t)row * DIMD);
    float s = 0.f;
    #pragma unroll
    for (int c4 = lane; c4 < 64; c4 += 32) {
        float4 x = v[c4];
        s += x.x*x.x + x.y*x.y + x.z*x.z + x.w*x.w;
        __half2 a = __floats2half2_rn(x.x, x.y);
        __half2 b = __floats2half2_rn(x.z, x.w);
        uint2 u;
        u.x = *(uint32_t*)&a; u.y = *(uint32_t*)&b;
        *(uint2*)(g_Bh + (size_t)row * DIMD + c4 * 4) = u;
    }
    #pragma unroll
    for (int o = 16; o; o >>= 1) s += __shfl_xor_sync(0xffffffffu, s, o);
    if (lane == 0) g_vnorm[row] = 0.5f * s;
}

// ============================ fp16 GEMM + fused top-2 ============================
__global__ __launch_bounds__(256, 1)
void gemm_kernel() {
    extern __shared__ char smem[];
    uint32_t sAu = smem_u32(smem);
    uint32_t sBu = sAu + SO_B;
    float* s_vn = (float*)(smem + SO_VN);
    float* r1a  = (float*)(smem + SO_R1);
    float* r2a  = (float*)(smem + SO_R2);
    int*   ria  = (int*)  (smem + SO_RI);

    const int tid = threadIdx.x, lane = tid & 31, wid = tid >> 5;
    const int wm = wid & 1, wn = wid >> 1;          // 2 x 4 warp grid
    const int bm = blockIdx.x & (MTILES - 1);
    const int bn = blockIdx.x >> 8;
    const int m0 = bm * 128, n0 = bn * 128;

    const char* Ab = (const char*)g_Ah + (size_t)m0 * 512;
    const char* Bb = (const char*)g_Bh + (size_t)n0 * 512;

    // issue all 4 k-chunks (each = A 16KB + B 16KB), one commit group each
    #pragma unroll
    for (int kc = 0; kc < 4; kc++) {
        #pragma unroll
        for (int q = 0; q < 4; q++) {
            int p = tid + 256 * q; int r = p >> 3, j = p & 7;
            cpasync16(sAu + kc * 16384 + swz(r * 128 + j * 16),
                      Ab + (size_t)r * 512 + kc * 128 + j * 16);
        }
        #pragma unroll
        for (int q = 0; q < 4; q++) {
            int p = tid + 256 * q; int r = p >> 3, j = p & 7;
            cpasync16(sBu + kc * 16384 + swz(r * 128 + j * 16),
                      Bb + (size_t)r * 512 + kc * 128 + j * 16);
        }
        CP_COMMIT();
    }
    if (tid < 128) s_vn[tid] = g_vnorm[n0 + tid];

    float acc[4][4][4];
    #pragma unroll
    for (int i = 0; i < 4; i++)
        #pragma unroll
        for (int j = 0; j < 4; j++)
            #pragma unroll
            for (int c = 0; c < 4; c++) acc[i][j][c] = 0.f;

#define COMPUTE_CHUNK(KC)                                                      \
    {                                                                          \
        uint32_t Abase = sAu + (KC) * 16384;                                   \
        uint32_t Bbase = sBu + (KC) * 16384;                                   \
        _Pragma("unroll")                                                      \
        for (int ks = 0; ks < 4; ks++) {                                       \
            uint32_t af[4][4];                                                 \
            _Pragma("unroll")                                                  \
            for (int mt = 0; mt < 4; mt++) {                                   \
                int row = wm * 64 + mt * 16 + (lane & 15);                     \
                uint32_t ad = Abase + swz(row * 128 + ks * 32 + (lane >> 4) * 16); \
                ldsm4(af[mt][0], af[mt][1], af[mt][2], af[mt][3], ad);         \
            }                                                                  \
            uint32_t bf[2][4];                                                 \
            _Pragma("unroll")                                                  \
            for (int np = 0; np < 2; np++) {                                   \
                int row = wn * 32 + np * 16 + (lane & 15);                     \
                uint32_t bd = Bbase + swz(row * 128 + ks * 32 + (lane >> 4) * 16); \
                ldsm4(bf[np][0], bf[np][1], bf[np][2], bf[np][3], bd);         \
            }                                                                  \
            _Pragma("unroll")                                                  \
            for (int mt = 0; mt < 4; mt++) {                                   \
                _Pragma("unroll")                                              \
                for (int nt = 0; nt < 4; nt++) {                               \
                    int np = nt >> 1, sub = nt & 1;                            \
                    mma16816(acc[mt][nt], af[mt], bf[np][sub], bf[np][sub + 2]); \
                }                                                              \
            }                                                                  \
        }                                                                      \
    }

    CP_WAIT(3); __syncthreads(); COMPUTE_CHUNK(0);
    CP_WAIT(2); __syncthreads(); COMPUTE_CHUNK(1);
    CP_WAIT(1); __syncthreads(); COMPUTE_CHUNK(2);
    CP_WAIT(0); __syncthreads(); COMPUTE_CHUNK(3);
#undef COMPUTE_CHUNK

    // ---- fused top-2 epilogue ----
    float m1[8], m2[8]; int i1[8];                 // slot = mt*2 + rowgroup
    #pragma unroll
    for (int s = 0; s < 8; s++) { m1[s] = FLT_MAX; m2[s] = FLT_MAX; i1[s] = 0x7FFFFFFF; }

    #pragma unroll
    for (int nt = 0; nt < 4; nt++) {
        int nloc_base = wn * 32 + (nt >> 1) * 16 + (nt & 1) * 8 + (lane & 3) * 2;
        #pragma unroll
        for (int c = 0; c < 2; c++) {
            int nloc = nloc_base + c;
            float vn = s_vn[nloc];
            int n = n0 + nloc;
            #pragma unroll
            for (int mt = 0; mt < 4; mt++) {
                #pragma unroll
                for (int rg = 0; rg < 2; rg++) {
                    int s_ = mt * 2 + rg;
                    float sc = vn - acc[mt][nt][rg * 2 + c];
                    if (sc < m1[s_]) { m2[s_] = m1[s_]; m1[s_] = sc; i1[s_] = n; }
                    else if (sc < m2[s_]) m2[s_] = sc;
                }
            }
        }
    }

    // quad reduce (cols live in lanes with same lane>>2)
    #pragma unroll
    for (int s = 0; s < 8; s++) {
        #pragma unroll
        for (int off = 1; off <= 2; off <<= 1) {
            float om1 = __shfl_xor_sync(0xffffffffu, m1[s], off);
            float om2 = __shfl_xor_sync(0xffffffffu, m2[s], off);
            int   oi  = __shfl_xor_sync(0xffffffffu, i1[s], off);
            if (om1 < m1[s] || (om1 == m1[s] && oi < i1[s])) {
                m2[s] = fminf(m1[s], om2); m1[s] = om1; i1[s] = oi;
            } else {
                m2[s] = fminf(m2[s], om1);
            }
        }
    }
    if ((lane & 3) == 0) {
        #pragma unroll
        for (int mt = 0; mt < 4; mt++)
            #pragma unroll
            for (int rg = 0; rg < 2; rg++) {
                int s_ = mt * 2 + rg;
                int row = wm * 64 + mt * 16 + rg * 8 + (lane >> 2);
                r1a[row * 4 + wn] = m1[s_];
                r2a[row * 4 + wn] = m2[s_];
                ria[row * 4 + wn] = i1[s_];
            }
    }
    __syncthreads();

    if (tid < 128) {
        float M1 = FLT_MAX, M2 = FLT_MAX; int I1 = 0x7FFFFFFF;
        #pragma unroll
        for (int w = 0; w < 4; w++) {
            float a1 = r1a[tid * 4 + w], a2 = r2a[tid * 4 + w];
            int   ai = ria[tid * 4 + w];
            if (a1 < M1 || (a1 == M1 && ai < I1)) {
                M2 = fminf(M1, a2); M1 = a1; I1 = ai;
            } else {
                M2 = fminf(M2, a1);
            }
        }
        int token = m0 + tid;
        g_s1[(size_t)bn * NTOK + token] = M1;
        g_s2[(size_t)bn * NTOK + token] = M2;
        g_i1[(size_t)bn * NTOK + token] = I1;
    }
}

// ============================ reduce + flag ============================
__global__ void reduce_kernel() {
    int t = blockIdx.x * blockDim.x + threadIdx.x;
    float m1 = FLT_MAX, m2 = FLT_MAX; int i1 = 0x7FFFFFFF;
    for (int nt = 0; nt < NTIL; nt++) {
        float s1 = g_s1[(size_t)nt * NTOK + t];
        float s2 = g_s2[(size_t)nt * NTOK + t];
        int   ii = g_i1[(size_t)nt * NTOK + t];
        if (s1 < m1 || (s1 == m1 && ii < i1)) {
            m2 = fminf(m1, s2); m1 = s1; i1 = ii;
        } else {
            m2 = fminf(m2, s1);
        }
    }
    g_idx[t] = i1;
    if (m2 - m1 < TAU) {
        g_key[t] = 0xFFFFFFFFFFFFFFFFull;
        __threadfence();
        int slot = atomicAdd(&g_wlcount, 1);
        g_wl[slot] = t;
    }
}

// ============== exact fp32 cleanup: (32-token group) x (1024-codeword slice) ==
#define CW   32          // tokens per work item
#define CSL  8           // vocab slices (KVOC/CSL = 1024 each)
#define CKC  32
__global__ __launch_bounds__(256, 2)
void cleanup_kernel(const float* __restrict__ seq, const float* __restrict__ vocab) {
    __shared__ float As[CKC][33];    // [k][m] (pad 33 -> conflict-free)
    __shared__ float Bs[CKC][132];   // [k][n]
    __shared__ int   tk[CW];

    const int nf = g_wlcount;
    if (nf == 0) return;
    const int ngrp   = (nf + CW - 1) / CW;
    const int nitems = ngrp * CSL;

    const int tid = threadIdx.x;
    const int tm  = tid >> 4;        // 0..15 -> token rows tm*2, tm*2+1
    const int tn  = tid & 15;        // 0..15 -> 8 codeword cols
    const int lk  = tid & 31;
    const int lm  = tid >> 5;        // 0..7

    for (int item = blockIdx.x; item < nitems; item += gridDim.x) {
        const int tg    = item / CSL;
        const int nbase = (item % CSL) * (KVOC / CSL);

        __syncthreads();   // protect tk across iterations
        if (tid < CW) {
            int w = tg * CW + tid;
            tk[tid] = g_wl[w < nf ? w : (nf - 1)];
        }
        __syncthreads();

        float minv[2]; int mini[2];
        minv[0] = minv[1] = FLT_MAX; mini[0] = mini[1] = 0;

        for (int n0 = nbase; n0 < nbase + KVOC / CSL; n0 += 128) {
            float acc[2][8];
            #pragma unroll
            for (int i = 0; i < 2; i++)
                #pragma unroll
                for (int j = 0; j < 8; j++) acc[i][j] = 0.f;

            for (int kc = 0; kc < DIMD; kc += CKC) {
                __syncthreads();
                #pragma unroll
                for (int m = lm; m < CW; m += 8)
                    As[lk][m] = seq[(size_t)tk[m] * DIMD + kc + lk];
                #pragma unroll
                for (int n = lm; n < 128; n += 8)
                    Bs[lk][n] = vocab[(size_t)(n0 + n) * DIMD + kc + lk];
                __syncthreads();

                #pragma unroll 8
                for (int k = 0; k < CKC; k++) {
                    float a0 = As[k][tm * 2];
                    float a1 = As[k][tm * 2 + 1];
                    float4 b0 = *(const float4*)&Bs[k][tn * 8];
                    float4 b1 = *(const float4*)&Bs[k][tn * 8 + 4];
                    float b[8] = {b0.x, b0.y, b0.z, b0.w, b1.x, b1.y, b1.z, b1.w};
                    #pragma unroll
                    for (int j = 0; j < 8; j++) {
                        acc[0][j] += a0 * b[j];
                        acc[1][j] += a1 * b[j];
                    }
                }
            }
            #pragma unroll
            for (int j = 0; j < 8; j++) {
                int n = n0 + tn * 8 + j;
                float vn = g_vnorm[n];
                #pragma unroll
                for (int i = 0; i < 2; i++) {
                    float sc = vn - acc[i][j];
                    if (sc < minv[i]) { minv[i] = sc; mini[i] = n; }
                }
            }
        }

        // reduce across the 16 tn-threads (16-lane groups)
        #pragma unroll
        for (int off = 8; off; off >>= 1) {
            #pragma unroll
            for (int i = 0; i < 2; i++) {
                float ov = __shfl_down_sync(0xffffffffu, minv[i], off, 16);
                int   oi = __shfl_down_sync(0xffffffffu, mini[i], off, 16);
                if (ov < minv[i] || (ov == minv[i] && oi < mini[i])) {
                    minv[i] = ov; mini[i] = oi;
                }
            }
        }
        if (tn == 0) {
            #pragma unroll
            for (int i = 0; i < 2; i++) {
                int row = tm * 2 + i;
                unsigned long long key =
                    ((unsigned long long)f2ord(minv[i]) << 32) | (uint32_t)mini[i];
                atomicMin(&g_key[tk[row]], key);
            }
        }
    }
}

__global__ void writeback_kernel() {
    int nf = g_wlcount;
    for (int f = blockIdx.x * blockDim.x + threadIdx.x; f < nf;
         f += gridDim.x * blockDim.x) {
        int t = g_wl[f];
        g_idx[t] = (int)(unsigned)(g_key[t] & 0xFFFFFFFFull);
    }
}

// ============================ gather ============================
__global__ void gather_kernel(const float* __restrict__ vocab,
                              float* __restrict__ out, int write_idx) {
    int token = blockIdx.x * 4 + (threadIdx.x >> 6);
    int l     = threadIdx.x & 63;
    int idx   = g_idx[token];
    const float4* src = (const float4*)(vocab + (size_t)idx * DIMD);
    float4*       dst = (float4*)(out + (size_t)token * DIMD);
    dst[l] = src[l];
    if (write_idx && l == 0)
        out[(size_t)NTOK * DIMD + token] = (float)idx;
}

// ============================ launch ============================
extern "C" void kernel_launch(void* const* d_in, const int* in_sizes, int n_in,
                              void* d_out, int out_size) {
    const float* seq   = (const float*)d_in[0];
    const float* vocab = (const float*)d_in[1];
    float* out = (float*)d_out;
    int write_idx = (out_size >= NTOK * DIMD + NTOK) ? 1 : 0;

    cudaFuncSetAttribute(gemm_kernel,
                         cudaFuncAttributeMaxDynamicSharedMemorySize, SM_TOTAL);

    split_seq_kernel<<<(NTOK * DIMD / 4) / 256, 256>>>(seq);
    split_vocab_kernel<<<KVOC / 8, 256>>>(vocab);
    gemm_kernel<<<MTILES * NTIL, 256, SM_TOTAL>>>();
    reduce_kernel<<<NTOK / 128, 128>>>();
    cleanup_kernel<<<512, 256>>>(seq, vocab);
    writeback_kernel<<<16, 256>>>();
    gather_kernel<<<NTOK / 4, 256>>>(vocab, out, write_idx);
}

// round 5
// speedup vs baseline: 3.1680x; 1.0015x over previous
#include <cuda_runtime.h>
#include <cuda_fp16.h>
#include <cstdint>
#include <float.h>

#define NTOK 32768
#define DIMD 256
#define KVOC 8192
#define MTILES 256          // m-tiles of 128 tokens
#define NTIL   64           // n-tiles of 128 codewords
#define TAU  0.08f

// ---- device scratch ----
__device__ __half g_Ah[(size_t)NTOK * DIMD];   // 16 MB fp16 tokens
__device__ __half g_Bh[(size_t)KVOC * DIMD];   // 4 MB fp16 vocab
__device__ float  g_vnorm[KVOC];               // 0.5*||v||^2 fp32
__device__ float  g_s1[(size_t)NTIL * NTOK];
__device__ float  g_s2[(size_t)NTIL * NTOK];
__device__ int    g_i1[(size_t)NTIL * NTOK];
__device__ int    g_idx[NTOK];
__device__ unsigned long long g_key[NTOK];
__device__ int    g_wl[NTOK];
__device__ int    g_wlcount;

// ---- smem offsets for gemm kernel ----
#define SO_A   0
#define SO_B   65536
#define SO_VN  131072
#define SO_R1  131584
#define SO_R2  133632
#define SO_RI  135680
#define SM_TOTAL 137728

// ============================ asm helpers ============================
__device__ __forceinline__ uint32_t smem_u32(const void* p) {
    uint32_t a;
    asm("{ .reg .u64 t; cvta.to.shared.u64 t, %1; cvt.u32.u64 %0, t; }"
        : "=r"(a) : "l"(p));
    return a;
}
__device__ __forceinline__ void cpasync16(uint32_t s, const void* g) {
    asm volatile("cp.async.cg.shared.global [%0], [%1], 16;" :: "r"(s), "l"(g));
}
#define CP_COMMIT() asm volatile("cp.async.commit_group;" ::: "memory")
#define CP_WAIT(N)  asm volatile("cp.async.wait_group " #N ";" ::: "memory")

__device__ __forceinline__ void ldsm4(uint32_t& r0, uint32_t& r1, uint32_t& r2,
                                      uint32_t& r3, uint32_t addr) {
    asm volatile("ldmatrix.sync.aligned.m8n8.x4.shared.b16 {%0,%1,%2,%3}, [%4];"
                 : "=r"(r0), "=r"(r1), "=r"(r2), "=r"(r3) : "r"(addr));
}
__device__ __forceinline__ void mma16816(float* d, const uint32_t* a,
                                         uint32_t b0, uint32_t b1) {
    asm volatile(
        "mma.sync.aligned.m16n8k16.row.col.f32.f16.f16.f32 "
        "{%0,%1,%2,%3},{%4,%5,%6,%7},{%8,%9},{%0,%1,%2,%3};"
        : "+f"(d[0]), "+f"(d[1]), "+f"(d[2]), "+f"(d[3])
        : "r"(a[0]), "r"(a[1]), "r"(a[2]), "r"(a[3]), "r"(b0), "r"(b1));
}
__device__ __forceinline__ uint32_t swz(uint32_t off) {
    return off ^ ((off >> 3) & 0x70);
}
// monotone float -> uint mapping (order preserving incl. negatives)
__device__ __forceinline__ uint32_t f2ord(float s) {
    uint32_t fb = __float_as_uint(s);
    return (fb & 0x80000000u) ? ~fb : (fb | 0x80000000u);
}

// ============================ convert kernels ============================
__global__ void split_seq_kernel(const float* __restrict__ seq) {
    if (blockIdx.x == 0 && threadIdx.x == 0) g_wlcount = 0;
    int idx = blockIdx.x * blockDim.x + threadIdx.x;   // one float4 each
    int row = idx >> 6;
    int c4  = idx & 63;
    float4 x = ((const float4*)seq)[idx];
    __half2 a = __floats2half2_rn(x.x, x.y);
    __half2 b = __floats2half2_rn(x.z, x.w);
    uint2 u;
    u.x = *(uint32_t*)&a; u.y = *(uint32_t*)&b;
    *(uint2*)(g_Ah + (size_t)row * DIMD + c4 * 4) = u;
}

__global__ void split_vocab_kernel(const float* __restrict__ vocab) {
    int row  = blockIdx.x * 8 + (threadIdx.x >> 5);
    int lane = threadIdx.x & 31;
    const float4* v = (const float4*)(vocab + (size_t)row * DIMD);
    float s = 0.f;
    #pragma unroll
    for (int c4 = lane; c4 < 64; c4 += 32) {
        float4 x = v[c4];
        s += x.x*x.x + x.y*x.y + x.z*x.z + x.w*x.w;
        __half2 a = __floats2half2_rn(x.x, x.y);
        __half2 b = __floats2half2_rn(x.z, x.w);
        uint2 u;
        u.x = *(uint32_t*)&a; u.y = *(uint32_t*)&b;
        *(uint2*)(g_Bh + (size_t)row * DIMD + c4 * 4) = u;
    }
    #pragma unroll
    for (int o = 16; o; o >>= 1) s += __shfl_xor_sync(0xffffffffu, s, o);
    if (lane == 0) g_vnorm[row] = 0.5f * s;
}

// ============================ fp16 GEMM + fused top-2 ============================
__global__ __launch_bounds__(256, 1)
void gemm_kernel() {
    extern __shared__ char smem[];
    uint32_t sAu = smem_u32(smem);
    uint32_t sBu = sAu + SO_B;
    float* s_vn = (float*)(smem + SO_VN);
    float* r1a  = (float*)(smem + SO_R1);
    float* r2a  = (float*)(smem + SO_R2);
    int*   ria  = (int*)  (smem + SO_RI);

    const int tid = threadIdx.x, lane = tid & 31, wid = tid >> 5;
    const int wm = wid & 1, wn = wid >> 1;          // 2 x 4 warp grid
    const int bm = blockIdx.x & (MTILES - 1);
    const int bn = blockIdx.x >> 8;
    const int m0 = bm * 128, n0 = bn * 128;

    const char* Ab = (const char*)g_Ah + (size_t)m0 * 512;
    const char* Bb = (const char*)g_Bh + (size_t)n0 * 512;

    // issue all 4 k-chunks (each = A 16KB + B 16KB), one commit group each
    #pragma unroll
    for (int kc = 0; kc < 4; kc++) {
        #pragma unroll
        for (int q = 0; q < 4; q++) {
            int p = tid + 256 * q; int r = p >> 3, j = p & 7;
            cpasync16(sAu + kc * 16384 + swz(r * 128 + j * 16),
                      Ab + (size_t)r * 512 + kc * 128 + j * 16);
        }
        #pragma unroll
        for (int q = 0; q < 4; q++) {
            int p = tid + 256 * q; int r = p >> 3, j = p & 7;
            cpasync16(sBu + kc * 16384 + swz(r * 128 + j * 16),
                      Bb + (size_t)r * 512 + kc * 128 + j * 16);
        }
        CP_COMMIT();
    }
    if (tid < 128) s_vn[tid] = g_vnorm[n0 + tid];

    float acc[4][4][4];
    #pragma unroll
    for (int i = 0; i < 4; i++)
        #pragma unroll
        for (int j = 0; j < 4; j++)
            #pragma unroll
            for (int c = 0; c < 4; c++) acc[i][j][c] = 0.f;

#define COMPUTE_CHUNK(KC)                                                      \
    {                                                                          \
        uint32_t Abase = sAu + (KC) * 16384;                                   \
        uint32_t Bbase = sBu + (KC) * 16384;                                   \
        _Pragma("unroll")                                                      \
        for (int ks = 0; ks < 4; ks++) {                                       \
            uint32_t af[4][4];                                                 \
            _Pragma("unroll")                                                  \
            for (int mt = 0; mt < 4; mt++) {                                   \
                int row = wm * 64 + mt * 16 + (lane & 15);                     \
                uint32_t ad = Abase + swz(row * 128 + ks * 32 + (lane >> 4) * 16); \
                ldsm4(af[mt][0], af[mt][1], af[mt][2], af[mt][3], ad);         \
            }                                                                  \
            uint32_t bf[2][4];                                                 \
            _Pragma("unroll")                                                  \
            for (int np = 0; np < 2; np++) {                                   \
                int row = wn * 32 + np * 16 + (lane & 15);                     \
                uint32_t bd = Bbase + swz(row * 128 + ks * 32 + (lane >> 4) * 16); \
                ldsm4(bf[np][0], bf[np][1], bf[np][2], bf[np][3], bd);         \
            }                                                                  \
            _Pragma("unroll")                                                  \
            for (int mt = 0; mt < 4; mt++) {                                   \
                _Pragma("unroll")                                              \
                for (int nt = 0; nt < 4; nt++) {                               \
                    int np = nt >> 1, sub = nt & 1;                            \
                    mma16816(acc[mt][nt], af[mt], bf[np][sub], bf[np][sub + 2]); \
                }                                                              \
            }                                                                  \
        }                                                                      \
    }

    CP_WAIT(3); __syncthreads(); COMPUTE_CHUNK(0);
    CP_WAIT(2); __syncthreads(); COMPUTE_CHUNK(1);
    CP_WAIT(1); __syncthreads(); COMPUTE_CHUNK(2);
    CP_WAIT(0); __syncthreads(); COMPUTE_CHUNK(3);
#undef COMPUTE_CHUNK

    // ---- fused top-2 epilogue ----
    float m1[8], m2[8]; int i1[8];                 // slot = mt*2 + rowgroup
    #pragma unroll
    for (int s = 0; s < 8; s++) { m1[s] = FLT_MAX; m2[s] = FLT_MAX; i1[s] = 0x7FFFFFFF; }

    #pragma unroll
    for (int nt = 0; nt < 4; nt++) {
        int nloc_base = wn * 32 + (nt >> 1) * 16 + (nt & 1) * 8 + (lane & 3) * 2;
        #pragma unroll
        for (int c = 0; c < 2; c++) {
            int nloc = nloc_base + c;
            float vn = s_vn[nloc];
            int n = n0 + nloc;
            #pragma unroll
            for (int mt = 0; mt < 4; mt++) {
                #pragma unroll
                for (int rg = 0; rg < 2; rg++) {
                    int s_ = mt * 2 + rg;
                    float sc = vn - acc[mt][nt][rg * 2 + c];
                    if (sc < m1[s_]) { m2[s_] = m1[s_]; m1[s_] = sc; i1[s_] = n; }
                    else if (sc < m2[s_]) m2[s_] = sc;
                }
            }
        }
    }

    // quad reduce (cols live in lanes with same lane>>2)
    #pragma unroll
    for (int s = 0; s < 8; s++) {
        #pragma unroll
        for (int off = 1; off <= 2; off <<= 1) {
            float om1 = __shfl_xor_sync(0xffffffffu, m1[s], off);
            float om2 = __shfl_xor_sync(0xffffffffu, m2[s], off);
            int   oi  = __shfl_xor_sync(0xffffffffu, i1[s], off);
            if (om1 < m1[s] || (om1 == m1[s] && oi < i1[s])) {
                m2[s] = fminf(m1[s], om2); m1[s] = om1; i1[s] = oi;
            } else {
                m2[s] = fminf(m2[s], om1);
            }
        }
    }
    if ((lane & 3) == 0) {
        #pragma unroll
        for (int mt = 0; mt < 4; mt++)
            #pragma unroll
            for (int rg = 0; rg < 2; rg++) {
                int s_ = mt * 2 + rg;
                int row = wm * 64 + mt * 16 + rg * 8 + (lane >> 2);
                r1a[row * 4 + wn] = m1[s_];
                r2a[row * 4 + wn] = m2[s_];
                ria[row * 4 + wn] = i1[s_];
            }
    }
    __syncthreads();

    if (tid < 128) {
        float M1 = FLT_MAX, M2 = FLT_MAX; int I1 = 0x7FFFFFFF;
        #pragma unroll
        for (int w = 0; w < 4; w++) {
            float a1 = r1a[tid * 4 + w], a2 = r2a[tid * 4 + w];
            int   ai = ria[tid * 4 + w];
            if (a1 < M1 || (a1 == M1 && ai < I1)) {
                M2 = fminf(M1, a2); M1 = a1; I1 = ai;
            } else {
                M2 = fminf(M2, a1);
            }
        }
        int token = m0 + tid;
        g_s1[(size_t)bn * NTOK + token] = M1;
        g_s2[(size_t)bn * NTOK + token] = M2;
        g_i1[(size_t)bn * NTOK + token] = I1;
    }
}

// ============================ reduce + flag ============================
__global__ void reduce_kernel() {
    int t = blockIdx.x * blockDim.x + threadIdx.x;
    float m1 = FLT_MAX, m2 = FLT_MAX; int i1 = 0x7FFFFFFF;
    for (int nt = 0; nt < NTIL; nt++) {
        float s1 = g_s1[(size_t)nt * NTOK + t];
        float s2 = g_s2[(size_t)nt * NTOK + t];
        int   ii = g_i1[(size_t)nt * NTOK + t];
        if (s1 < m1 || (s1 == m1 && ii < i1)) {
            m2 = fminf(m1, s2); m1 = s1; i1 = ii;
        } else {
            m2 = fminf(m2, s1);
        }
    }
    g_idx[t] = i1;
    if (m2 - m1 < TAU) {
        g_key[t] = 0xFFFFFFFFFFFFFFFFull;
        __threadfence();
        int slot = atomicAdd(&g_wlcount, 1);
        g_wl[slot] = t;
    }
}

// ============== exact fp32 cleanup: (32-token group) x (1024-codeword slice) ==
#define CW   32          // tokens per work item
#define CSL  8           // vocab slices (KVOC/CSL = 1024 each)
#define CKC  32
__global__ __launch_bounds__(256, 2)
void cleanup_kernel(const float* __restrict__ seq, const float* __restrict__ vocab) {
    __shared__ float As[CKC][33];    // [k][m] (pad 33 -> conflict-free)
    __shared__ float Bs[CKC][132];   // [k][n]
    __shared__ int   tk[CW];

    const int nf = g_wlcount;
    if (nf == 0) return;
    const int ngrp   = (nf + CW - 1) / CW;
    const int nitems = ngrp * CSL;

    const int tid = threadIdx.x;
    const int tm  = tid >> 4;        // 0..15 -> token rows tm*2, tm*2+1
    const int tn  = tid & 15;        // 0..15 -> 8 codeword cols
    const int lk  = tid & 31;
    const int lm  = tid >> 5;        // 0..7

    for (int item = blockIdx.x; item < nitems; item += gridDim.x) {
        const int tg    = item / CSL;
        const int nbase = (item % CSL) * (KVOC / CSL);

        __syncthreads();   // protect tk across iterations
        if (tid < CW) {
            int w = tg * CW + tid;
            tk[tid] = g_wl[w < nf ? w : (nf - 1)];
        }
        __syncthreads();

        float minv[2]; int mini[2];
        minv[0] = minv[1] = FLT_MAX; mini[0] = mini[1] = 0;

        for (int n0 = nbase; n0 < nbase + KVOC / CSL; n0 += 128) {
            float acc[2][8];
            #pragma unroll
            for (int i = 0; i < 2; i++)
                #pragma unroll
                for (int j = 0; j < 8; j++) acc[i][j] = 0.f;

            for (int kc = 0; kc < DIMD; kc += CKC) {
                __syncthreads();
                #pragma unroll
                for (int m = lm; m < CW; m += 8)
                    As[lk][m] = seq[(size_t)tk[m] * DIMD + kc + lk];
                #pragma unroll
                for (int n = lm; n < 128; n += 8)
                    Bs[lk][n] = vocab[(size_t)(n0 + n) * DIMD + kc + lk];
                __syncthreads();

                #pragma unroll 8
                for (int k = 0; k < CKC; k++) {
                    float a0 = As[k][tm * 2];
                    float a1 = As[k][tm * 2 + 1];
                    float4 b0 = *(const float4*)&Bs[k][tn * 8];
                    float4 b1 = *(const float4*)&Bs[k][tn * 8 + 4];
                    float b[8] = {b0.x, b0.y, b0.z, b0.w, b1.x, b1.y, b1.z, b1.w};
                    #pragma unroll
                    for (int j = 0; j < 8; j++) {
                        acc[0][j] += a0 * b[j];
                        acc[1][j] += a1 * b[j];
                    }
                }
            }
            #pragma unroll
            for (int j = 0; j < 8; j++) {
                int n = n0 + tn * 8 + j;
                float vn = g_vnorm[n];
                #pragma unroll
                for (int i = 0; i < 2; i++) {
                    float sc = vn - acc[i][j];
                    if (sc < minv[i]) { minv[i] = sc; mini[i] = n; }
                }
            }
        }

        // reduce across the 16 tn-threads (16-lane groups)
        #pragma unroll
        for (int off = 8; off; off >>= 1) {
            #pragma unroll
            for (int i = 0; i < 2; i++) {
                float ov = __shfl_down_sync(0xffffffffu, minv[i], off, 16);
                int   oi = __shfl_down_sync(0xffffffffu, mini[i], off, 16);
                if (ov < minv[i] || (ov == minv[i] && oi < mini[i])) {
                    minv[i] = ov; mini[i] = oi;
                }
            }
        }
        if (tn == 0) {
            #pragma unroll
            for (int i = 0; i < 2; i++) {
                int row = tm * 2 + i;
                unsigned long long key =
                    ((unsigned long long)f2ord(minv[i]) << 32) | (uint32_t)mini[i];
                atomicMin(&g_key[tk[row]], key);
            }
        }
    }
}

__global__ void writeback_kernel() {
    int nf = g_wlcount;
    for (int f = blockIdx.x * blockDim.x + threadIdx.x; f < nf;
         f += gridDim.x * blockDim.x) {
        int t = g_wl[f];
        g_idx[t] = (int)(unsigned)(g_key[t] & 0xFFFFFFFFull);
    }
}

// ============================ gather ============================
__global__ void gather_kernel(const float* __restrict__ vocab,
                              float* __restrict__ out, int write_idx) {
    int token = blockIdx.x * 4 + (threadIdx.x >> 6);
    int l     = threadIdx.x & 63;
    int idx   = g_idx[token];
    const float4* src = (const float4*)(vocab + (size_t)idx * DIMD);
    float4*       dst = (float4*)(out + (size_t)token * DIMD);
    dst[l] = src[l];
    if (write_idx && l == 0)
        out[(size_t)NTOK * DIMD + token] = (float)idx;
}

// ============================ launch ============================
extern "C" void kernel_launch(void* const* d_in, const int* in_sizes, int n_in,
                              void* d_out, int out_size) {
    const float* seq   = (const float*)d_in[0];
    const float* vocab = (const float*)d_in[1];
    float* out = (float*)d_out;
    int write_idx = (out_size >= NTOK * DIMD + NTOK) ? 1 : 0;

    cudaFuncSetAttribute(gemm_kernel,
                         cudaFuncAttributeMaxDynamicSharedMemorySize, SM_TOTAL);

    split_seq_kernel<<<(NTOK * DIMD / 4) / 256, 256>>>(seq);
    split_vocab_kernel<<<KVOC / 8, 256>>>(vocab);
    gemm_kernel<<<MTILES * NTIL, 256, SM_TOTAL>>>();
    reduce_kernel<<<NTOK / 128, 128>>>();
    cleanup_kernel<<<512, 256>>>(seq, vocab);
    writeback_kernel<<<16, 256>>>();
    gather_kernel<<<NTOK / 4, 256>>>(vocab, out, write_idx);
}

// round 6
// speedup vs baseline: 3.8869x; 1.2270x over previous
#include <cuda_runtime.h>
#include <cuda_fp16.h>
#include <cstdint>
#include <float.h>

#define NTOK 32768
#define DIMD 256
#define KVOC 8192
#define MTILES 256          // m-tiles of 128 tokens
#define NTIL   64           // n-tiles of 128 codewords
#define TAU  0.08f

// ---- device scratch ----
__device__ __half g_Ah[(size_t)NTOK * DIMD];   // 16 MB fp16 tokens
__device__ __half g_Bh[(size_t)KVOC * DIMD];   // 4 MB fp16 vocab
__device__ float  g_vnorm[KVOC];               // 0.5*||v||^2 fp32
__device__ float  g_s1[(size_t)NTIL * NTOK];
__device__ float  g_s2[(size_t)NTIL * NTOK];
__device__ int    g_i1[(size_t)NTIL * NTOK];
__device__ int    g_idx[NTOK];
__device__ unsigned long long g_key[NTOK];
__device__ int    g_wl[NTOK];
__device__ int    g_wlcount;

// ---- smem offsets for gemm kernel (2-stage pipeline) ----
// stage s (s=0,1): A chunk at s*32768, B chunk at s*32768+16384
#define SO_VN  65536
#define SO_R1  66048
#define SO_R2  68096
#define SO_RI  70144
#define SM_TOTAL 72192

// ============================ asm helpers ============================
__device__ __forceinline__ uint32_t smem_u32(const void* p) {
    uint32_t a;
    asm("{ .reg .u64 t; cvta.to.shared.u64 t, %1; cvt.u32.u64 %0, t; }"
        : "=r"(a) : "l"(p));
    return a;
}
__device__ __forceinline__ void cpasync16(uint32_t s, const void* g) {
    asm volatile("cp.async.cg.shared.global [%0], [%1], 16;" :: "r"(s), "l"(g));
}
#define CP_COMMIT() asm volatile("cp.async.commit_group;" ::: "memory")
#define CP_WAIT(N)  asm volatile("cp.async.wait_group " #N ";" ::: "memory")

__device__ __forceinline__ void ldsm4(uint32_t& r0, uint32_t& r1, uint32_t& r2,
                                      uint32_t& r3, uint32_t addr) {
    asm volatile("ldmatrix.sync.aligned.m8n8.x4.shared.b16 {%0,%1,%2,%3}, [%4];"
                 : "=r"(r0), "=r"(r1), "=r"(r2), "=r"(r3) : "r"(addr));
}
__device__ __forceinline__ void mma16816(float* d, const uint32_t* a,
                                         uint32_t b0, uint32_t b1) {
    asm volatile(
        "mma.sync.aligned.m16n8k16.row.col.f32.f16.f16.f32 "
        "{%0,%1,%2,%3},{%4,%5,%6,%7},{%8,%9},{%0,%1,%2,%3};"
        : "+f"(d[0]), "+f"(d[1]), "+f"(d[2]), "+f"(d[3])
        : "r"(a[0]), "r"(a[1]), "r"(a[2]), "r"(a[3]), "r"(b0), "r"(b1));
}
__device__ __forceinline__ uint32_t swz(uint32_t off) {
    return off ^ ((off >> 3) & 0x70);
}
// monotone float -> uint mapping (order preserving incl. negatives)
__device__ __forceinline__ uint32_t f2ord(float s) {
    uint32_t fb = __float_as_uint(s);
    return (fb & 0x80000000u) ? ~fb : (fb | 0x80000000u);
}

// ============================ convert kernels ============================
__global__ void split_seq_kernel(const float* __restrict__ seq) {
    if (blockIdx.x == 0 && threadIdx.x == 0) g_wlcount = 0;
    int idx = blockIdx.x * blockDim.x + threadIdx.x;   // one float4 each
    int row = idx >> 6;
    int c4  = idx & 63;
    float4 x = ((const float4*)seq)[idx];
    __half2 a = __floats2half2_rn(x.x, x.y);
    __half2 b = __floats2half2_rn(x.z, x.w);
    uint2 u;
    u.x = *(uint32_t*)&a; u.y = *(uint32_t*)&b;
    *(uint2*)(g_Ah + (size_t)row * DIMD + c4 * 4) = u;
}

__global__ void split_vocab_kernel(const float* __restrict__ vocab) {
    int row  = blockIdx.x * 8 + (threadIdx.x >> 5);
    int lane = threadIdx.x & 31;
    const float4* v = (const float4*)(vocab + (size_t)row * DIMD);
    float s = 0.f;
    #pragma unroll
    for (int c4 = lane; c4 < 64; c4 += 32) {
        float4 x = v[c4];
        s += x.x*x.x + x.y*x.y + x.z*x.z + x.w*x.w;
        __half2 a = __floats2half2_rn(x.x, x.y);
        __half2 b = __floats2half2_rn(x.z, x.w);
        uint2 u;
        u.x = *(uint32_t*)&a; u.y = *(uint32_t*)&b;
        *(uint2*)(g_Bh + (size_t)row * DIMD + c4 * 4) = u;
    }
    #pragma unroll
    for (int o = 16; o; o >>= 1) s += __shfl_xor_sync(0xffffffffu, s, o);
    if (lane == 0) g_vnorm[row] = 0.5f * s;
}

// ============================ fp16 GEMM + fused top-2 ============================
__global__ __launch_bounds__(256, 2)
void gemm_kernel() {
    extern __shared__ char smem[];
    uint32_t sbase = smem_u32(smem);
    float* s_vn = (float*)(smem + SO_VN);
    float* r1a  = (float*)(smem + SO_R1);
    float* r2a  = (float*)(smem + SO_R2);
    int*   ria  = (int*)  (smem + SO_RI);

    const int tid = threadIdx.x, lane = tid & 31, wid = tid >> 5;
    const int wm = wid & 1, wn = wid >> 1;          // 2 x 4 warp grid
    const int bm = blockIdx.x & (MTILES - 1);
    const int bn = blockIdx.x >> 8;
    const int m0 = bm * 128, n0 = bn * 128;

    const char* Ab = (const char*)g_Ah + (size_t)m0 * 512;
    const char* Bb = (const char*)g_Bh + (size_t)n0 * 512;

    // load chunk kc (A 16KB + B 16KB) into stage buffer sb
#define LOAD_CHUNK(KC, SB)                                                     \
    {                                                                          \
        uint32_t stA = sbase + (SB) * 32768;                                   \
        uint32_t stB = stA + 16384;                                            \
        _Pragma("unroll")                                                      \
        for (int q = 0; q < 4; q++) {                                          \
            int p = tid + 256 * q; int r = p >> 3, j = p & 7;                  \
            cpasync16(stA + swz(r * 128 + j * 16),                             \
                      Ab + (size_t)r * 512 + (KC) * 128 + j * 16);             \
        }                                                                      \
        _Pragma("unroll")                                                      \
        for (int q = 0; q < 4; q++) {                                          \
            int p = tid + 256 * q; int r = p >> 3, j = p & 7;                  \
            cpasync16(stB + swz(r * 128 + j * 16),                             \
                      Bb + (size_t)r * 512 + (KC) * 128 + j * 16);             \
        }                                                                      \
        CP_COMMIT();                                                           \
    }

    LOAD_CHUNK(0, 0)
    LOAD_CHUNK(1, 1)
    if (tid < 128) s_vn[tid] = g_vnorm[n0 + tid];

    float acc[4][4][4];
    #pragma unroll
    for (int i = 0; i < 4; i++)
        #pragma unroll
        for (int j = 0; j < 4; j++)
            #pragma unroll
            for (int c = 0; c < 4; c++) acc[i][j][c] = 0.f;

#define COMPUTE_CHUNK(SB)                                                      \
    {                                                                          \
        uint32_t Abase = sbase + (SB) * 32768;                                 \
        uint32_t Bbase = Abase + 16384;                                        \
        _Pragma("unroll")                                                      \
        for (int ks = 0; ks < 4; ks++) {                                       \
            uint32_t af[4][4];                                                 \
            _Pragma("unroll")                                                  \
            for (int mt = 0; mt < 4; mt++) {                                   \
                int row = wm * 64 + mt * 16 + (lane & 15);                     \
                uint32_t ad = Abase + swz(row * 128 + ks * 32 + (lane >> 4) * 16); \
                ldsm4(af[mt][0], af[mt][1], af[mt][2], af[mt][3], ad);         \
            }                                                                  \
            uint32_t bf[2][4];                                                 \
            _Pragma("unroll")                                                  \
            for (int np = 0; np < 2; np++) {                                   \
                int row = wn * 32 + np * 16 + (lane & 15);                     \
                uint32_t bd = Bbase + swz(row * 128 + ks * 32 + (lane >> 4) * 16); \
                ldsm4(bf[np][0], bf[np][1], bf[np][2], bf[np][3], bd);         \
            }                                                                  \
            _Pragma("unroll")                                                  \
            for (int mt = 0; mt < 4; mt++) {                                   \
                _Pragma("unroll")                                              \
                for (int nt = 0; nt < 4; nt++) {                               \
                    int np = nt >> 1, sub = nt & 1;                            \
                    mma16816(acc[mt][nt], af[mt], bf[np][sub], bf[np][sub + 2]); \
                }                                                              \
            }                                                                  \
        }                                                                      \
    }

    // 2-stage pipeline over 4 K-chunks
    CP_WAIT(1); __syncthreads(); COMPUTE_CHUNK(0);
    __syncthreads(); LOAD_CHUNK(2, 0)
    CP_WAIT(1); __syncthreads(); COMPUTE_CHUNK(1);
    __syncthreads(); LOAD_CHUNK(3, 1)
    CP_WAIT(1); __syncthreads(); COMPUTE_CHUNK(0);
    CP_WAIT(0); __syncthreads(); COMPUTE_CHUNK(1);
#undef COMPUTE_CHUNK
#undef LOAD_CHUNK

    // ---- fused top-2 epilogue ----
    float m1[8], m2[8]; int i1[8];                 // slot = mt*2 + rowgroup
    #pragma unroll
    for (int s = 0; s < 8; s++) { m1[s] = FLT_MAX; m2[s] = FLT_MAX; i1[s] = 0x7FFFFFFF; }

    #pragma unroll
    for (int nt = 0; nt < 4; nt++) {
        int nloc_base = wn * 32 + (nt >> 1) * 16 + (nt & 1) * 8 + (lane & 3) * 2;
        #pragma unroll
        for (int c = 0; c < 2; c++) {
            int nloc = nloc_base + c;
            float vn = s_vn[nloc];
            int n = n0 + nloc;
            #pragma unroll
            for (int mt = 0; mt < 4; mt++) {
                #pragma unroll
                for (int rg = 0; rg < 2; rg++) {
                    int s_ = mt * 2 + rg;
                    float sc = vn - acc[mt][nt][rg * 2 + c];
                    if (sc < m1[s_]) { m2[s_] = m1[s_]; m1[s_] = sc; i1[s_] = n; }
                    else if (sc < m2[s_]) m2[s_] = sc;
                }
            }
        }
    }

    // quad reduce (cols live in lanes with same lane>>2)
    #pragma unroll
    for (int s = 0; s < 8; s++) {
        #pragma unroll
        for (int off = 1; off <= 2; off <<= 1) {
            float om1 = __shfl_xor_sync(0xffffffffu, m1[s], off);
            float om2 = __shfl_xor_sync(0xffffffffu, m2[s], off);
            int   oi  = __shfl_xor_sync(0xffffffffu, i1[s], off);
            if (om1 < m1[s] || (om1 == m1[s] && oi < i1[s])) {
                m2[s] = fminf(m1[s], om2); m1[s] = om1; i1[s] = oi;
            } else {
                m2[s] = fminf(m2[s], om1);
            }
        }
    }
    if ((lane & 3) == 0) {
        #pragma unroll
        for (int mt = 0; mt < 4; mt++)
            #pragma unroll
            for (int rg = 0; rg < 2; rg++) {
                int s_ = mt * 2 + rg;
                int row = wm * 64 + mt * 16 + rg * 8 + (lane >> 2);
                r1a[row * 4 + wn] = m1[s_];
                r2a[row * 4 + wn] = m2[s_];
                ria[row * 4 + wn] = i1[s_];
            }
    }
    __syncthreads();

    if (tid < 128) {
        float M1 = FLT_MAX, M2 = FLT_MAX; int I1 = 0x7FFFFFFF;
        #pragma unroll
        for (int w = 0; w < 4; w++) {
            float a1 = r1a[tid * 4 + w], a2 = r2a[tid * 4 + w];
            int   ai = ria[tid * 4 + w];
            if (a1 < M1 || (a1 == M1 && ai < I1)) {
                M2 = fminf(M1, a2); M1 = a1; I1 = ai;
            } else {
                M2 = fminf(M2, a1);
            }
        }
        int token = m0 + tid;
        g_s1[(size_t)bn * NTOK + token] = M1;
        g_s2[(size_t)bn * NTOK + token] = M2;
        g_i1[(size_t)bn * NTOK + token] = I1;
    }
}

// ============================ reduce + flag ============================
__global__ void reduce_kernel() {
    int t = blockIdx.x * blockDim.x + threadIdx.x;
    float m1 = FLT_MAX, m2 = FLT_MAX; int i1 = 0x7FFFFFFF;
    for (int nt = 0; nt < NTIL; nt++) {
        float s1 = g_s1[(size_t)nt * NTOK + t];
        float s2 = g_s2[(size_t)nt * NTOK + t];
        int   ii = g_i1[(size_t)nt * NTOK + t];
        if (s1 < m1 || (s1 == m1 && ii < i1)) {
            m2 = fminf(m1, s2); m1 = s1; i1 = ii;
        } else {
            m2 = fminf(m2, s1);
        }
    }
    g_idx[t] = i1;
    if (m2 - m1 < TAU) {
        g_key[t] = 0xFFFFFFFFFFFFFFFFull;
        __threadfence();
        int slot = atomicAdd(&g_wlcount, 1);
        g_wl[slot] = t;
    }
}

// ============== exact fp32 cleanup: (32-token group) x (1024-codeword slice) ==
#define CW   32          // tokens per work item
#define CSL  8           // vocab slices (KVOC/CSL = 1024 each)
#define CKC  32
__global__ __launch_bounds__(256, 2)
void cleanup_kernel(const float* __restrict__ seq, const float* __restrict__ vocab) {
    __shared__ float As[CKC][33];    // [k][m] (pad 33 -> conflict-free)
    __shared__ float Bs[CKC][132];   // [k][n]
    __shared__ int   tk[CW];

    const int nf = g_wlcount;
    if (nf == 0) return;
    const int ngrp   = (nf + CW - 1) / CW;
    const int nitems = ngrp * CSL;

    const int tid = threadIdx.x;
    const int tm  = tid >> 4;        // 0..15 -> token rows tm*2, tm*2+1
    const int tn  = tid & 15;        // 0..15 -> 8 codeword cols
    const int lk  = tid & 31;
    const int lm  = tid >> 5;        // 0..7

    for (int item = blockIdx.x; item < nitems; item += gridDim.x) {
        const int tg    = item / CSL;
        const int nbase = (item % CSL) * (KVOC / CSL);

        __syncthreads();   // protect tk across iterations
        if (tid < CW) {
            int w = tg * CW + tid;
            tk[tid] = g_wl[w < nf ? w : (nf - 1)];
        }
        __syncthreads();

        float minv[2]; int mini[2];
        minv[0] = minv[1] = FLT_MAX; mini[0] = mini[1] = 0;

        for (int n0 = nbase; n0 < nbase + KVOC / CSL; n0 += 128) {
            float acc[2][8];
            #pragma unroll
            for (int i = 0; i < 2; i++)
                #pragma unroll
                for (int j = 0; j < 8; j++) acc[i][j] = 0.f;

            for (int kc = 0; kc < DIMD; kc += CKC) {
                __syncthreads();
                #pragma unroll
                for (int m = lm; m < CW; m += 8)
                    As[lk][m] = seq[(size_t)tk[m] * DIMD + kc + lk];
                #pragma unroll
                for (int n = lm; n < 128; n += 8)
                    Bs[lk][n] = vocab[(size_t)(n0 + n) * DIMD + kc + lk];
                __syncthreads();

                #pragma unroll 8
                for (int k = 0; k < CKC; k++) {
                    float a0 = As[k][tm * 2];
                    float a1 = As[k][tm * 2 + 1];
                    float4 b0 = *(const float4*)&Bs[k][tn * 8];
                    float4 b1 = *(const float4*)&Bs[k][tn * 8 + 4];
                    float b[8] = {b0.x, b0.y, b0.z, b0.w, b1.x, b1.y, b1.z, b1.w};
                    #pragma unroll
                    for (int j = 0; j < 8; j++) {
                        acc[0][j] += a0 * b[j];
                        acc[1][j] += a1 * b[j];
                    }
                }
            }
            #pragma unroll
            for (int j = 0; j < 8; j++) {
                int n = n0 + tn * 8 + j;
                float vn = g_vnorm[n];
                #pragma unroll
                for (int i = 0; i < 2; i++) {
                    float sc = vn - acc[i][j];
                    if (sc < minv[i]) { minv[i] = sc; mini[i] = n; }
                }
            }
        }

        // reduce across the 16 tn-threads (16-lane groups)
        #pragma unroll
        for (int off = 8; off; off >>= 1) {
            #pragma unroll
            for (int i = 0; i < 2; i++) {
                float ov = __shfl_down_sync(0xffffffffu, minv[i], off, 16);
                int   oi = __shfl_down_sync(0xffffffffu, mini[i], off, 16);
                if (ov < minv[i] || (ov == minv[i] && oi < mini[i])) {
                    minv[i] = ov; mini[i] = oi;
                }
            }
        }
        if (tn == 0) {
            #pragma unroll
            for (int i = 0; i < 2; i++) {
                int row = tm * 2 + i;
                unsigned long long key =
                    ((unsigned long long)f2ord(minv[i]) << 32) | (uint32_t)mini[i];
                atomicMin(&g_key[tk[row]], key);
            }
        }
    }
}

__global__ void writeback_kernel() {
    int nf = g_wlcount;
    for (int f = blockIdx.x * blockDim.x + threadIdx.x; f < nf;
         f += gridDim.x * blockDim.x) {
        int t = g_wl[f];
        g_idx[t] = (int)(unsigned)(g_key[t] & 0xFFFFFFFFull);
    }
}

// ============================ gather ============================
__global__ void gather_kernel(const float* __restrict__ vocab,
                              float* __restrict__ out, int write_idx) {
    int token = blockIdx.x * 4 + (threadIdx.x >> 6);
    int l     = threadIdx.x & 63;
    int idx   = g_idx[token];
    const float4* src = (const float4*)(vocab + (size_t)idx * DIMD);
    float4*       dst = (float4*)(out + (size_t)token * DIMD);
    dst[l] = src[l];
    if (write_idx && l == 0)
        out[(size_t)NTOK * DIMD + token] = (float)idx;
}

// ============================ launch ============================
extern "C" void kernel_launch(void* const* d_in, const int* in_sizes, int n_in,
                              void* d_out, int out_size) {
    const float* seq   = (const float*)d_in[0];
    const float* vocab = (const float*)d_in[1];
    float* out = (float*)d_out;
    int write_idx = (out_size >= NTOK * DIMD + NTOK) ? 1 : 0;

    cudaFuncSetAttribute(gemm_kernel,
                         cudaFuncAttributeMaxDynamicSharedMemorySize, SM_TOTAL);

    split_seq_kernel<<<(NTOK * DIMD / 4) / 256, 256>>>(seq);
    split_vocab_kernel<<<KVOC / 8, 256>>>(vocab);
    gemm_kernel<<<MTILES * NTIL, 256, SM_TOTAL>>>();
    reduce_kernel<<<NTOK / 128, 128>>>();
    cleanup_kernel<<<512, 256>>>(seq, vocab);
    writeback_kernel<<<16, 256>>>();
    gather_kernel<<<NTOK / 4, 256>>>(vocab, out, write_idx);
}